// round 4
// baseline (speedup 1.0000x reference)
#include <cuda_runtime.h>
#include <cuda_bf16.h>

// SSM kernel: out[l, i] = exp(l * a_i) * (B_i * C_i) + D,  a_i = A[i][i]
// L = 262144, n = 256. Output 256 MiB fp32 -> pure streaming-store bound.
//
// R1: geometric recurrence (no per-element exp).         45.2us k / 5.94 TB/s
// R2: balanced grid 592=148*4, 256 thr.                  42.6us k / 6.30 TB/s
// R3: 512 thr (64 warps/SM) -> REGRESSED (queue contention). 43.7us / 6.14
// R4: go the other way: 2 CTAs/SM (296 blocks, 16 warps/SM), finer 32-row
//     chunks. Stores are issue-only; 16 warps still oversubscribe the store
//     path ~10x, while contention + dynamic power drop (DVFS headroom on the
//     ~6300 B/cyc LTS write cap).

#define N_COLS 256
#define CGROUPS 64              // 64 float4 per row
#define CHUNK_ROWS 32           // rows per chunk per block per grid-stride step
#define TY 4                    // row sub-chunks per block (256 threads / 64)
#define RPT 8                   // rows per thread per chunk (CHUNK_ROWS/TY)
#define GRID_BLOCKS 296         // 148 SMs * 2 CTAs, exactly balanced

__global__ __launch_bounds__(256, 2)
void ssm_kernel(const float* __restrict__ A,
                const float* __restrict__ B,
                const float* __restrict__ C,
                const float* __restrict__ D,
                float4* __restrict__ out,
                int nchunks)
{
    const int tx = threadIdx.x & 63;        // column group: cols 4*tx .. 4*tx+3
    const int ty = threadIdx.x >> 6;        // row sub-chunk within chunk (0..3)

    const float d = D[0];
    const float LOG2E = 1.4426950408889634f;

    // rows skipped hopping from the end of this thread's rows in one chunk
    // to the start of its rows in its next grid-stride chunk
    const float hop_rows = (float)((long long)gridDim.x * CHUNK_ROWS - RPT);

    const long long first_row = (long long)blockIdx.x * CHUNK_ROWS
                              + (long long)ty * RPT;

    float r[4], pm[4], bc[4], jmp[4];
#pragma unroll
    for (int k = 0; k < 4; k++) {
        const int j = tx * 4 + k;
        const float a = A[j * N_COLS + j];            // diag (strictly negative)
        r[k]   = __expf(a);                           // per-row decay ratio
        jmp[k] = exp2f(hop_rows * a * LOG2E);         // chunk-hop factor
        pm[k]  = exp2f((float)first_row * a * LOG2E); // exact anchor
        bc[k]  = B[j] * C[j];
    }

    for (int c = blockIdx.x; c < nchunks; c += gridDim.x) {
        long long base = ((long long)c * CHUNK_ROWS + (long long)ty * RPT)
                       * CGROUPS + tx;
#pragma unroll
        for (int l = 0; l < RPT; l++) {
            float4 v;
            v.x = fmaf(pm[0], bc[0], d);
            v.y = fmaf(pm[1], bc[1], d);
            v.z = fmaf(pm[2], bc[2], d);
            v.w = fmaf(pm[3], bc[3], d);
            __stcs(&out[base], v);                    // streaming store
            base += CGROUPS;
            pm[0] *= r[0];
            pm[1] *= r[1];
            pm[2] *= r[2];
            pm[3] *= r[3];
        }
        // hop to this thread's rows in the next grid-stride chunk
        pm[0] *= jmp[0];
        pm[1] *= jmp[1];
        pm[2] *= jmp[2];
        pm[3] *= jmp[3];
    }
}

extern "C" void kernel_launch(void* const* d_in, const int* in_sizes, int n_in,
                              void* d_out, int out_size)
{
    // Inputs per reference order: (optional scalar L), A (n*n), B (n), C (n), D (1)
    int base = 0;
    if (n_in >= 5) base = n_in - 4;
    const float* A = (const float*)d_in[base + 0];
    const float* B = (const float*)d_in[base + 1];
    const float* C = (const float*)d_in[base + 2];
    const float* D = (const float*)d_in[base + 3];

    const long long L = (long long)out_size / N_COLS;   // 262144
    const int nchunks = (int)(L / CHUNK_ROWS);          // 8192

    ssm_kernel<<<GRID_BLOCKS, 256>>>(A, B, C, D, (float4*)d_out, nchunks);
}

// round 5
// speedup vs baseline: 1.3529x; 1.3529x over previous
#include <cuda_runtime.h>
#include <cuda_bf16.h>

// SSM kernel: out[l, i] = exp(l * a_i) * (B_i * C_i) + D,  a_i = A[i][i]
// L = 262144, n = 256. Output 256 MiB fp32 -> pure streaming-store bound.
//
// Warp-count vs chip store throughput (measured):
//   16 w/SM -> 3.47 TB/s   (R4: store-issue starved, L1tex-bound)
//   32 w/SM -> 6.30 TB/s   (R2: best so far, 42.6us kernel)
//   64 w/SM -> 6.14 TB/s   (R3: queue contention)
// R5: bracket the peak with 48 w/SM: 444 blocks (148*3) x 256 threads,
//     64-row grid-stride chunks (per-SM imbalance ~1.2%).

#define N_COLS 256
#define CGROUPS 64              // 64 float4 per row
#define CHUNK_ROWS 64           // rows per chunk per block per grid-stride step
#define TY 4                    // row sub-chunks per block (256 threads / 64)
#define RPT 16                  // rows per thread per chunk (CHUNK_ROWS/TY)
#define GRID_BLOCKS 444         // 148 SMs * 3 CTAs

__global__ __launch_bounds__(256, 3)
void ssm_kernel(const float* __restrict__ A,
                const float* __restrict__ B,
                const float* __restrict__ C,
                const float* __restrict__ D,
                float4* __restrict__ out,
                int nchunks)
{
    const int tx = threadIdx.x & 63;        // column group: cols 4*tx .. 4*tx+3
    const int ty = threadIdx.x >> 6;        // row sub-chunk within chunk (0..3)

    const float d = D[0];
    const float LOG2E = 1.4426950408889634f;

    // rows skipped hopping from the end of this thread's rows in one chunk
    // to the start of its rows in its next grid-stride chunk
    const float hop_rows = (float)((long long)gridDim.x * CHUNK_ROWS - RPT);

    const long long first_row = (long long)blockIdx.x * CHUNK_ROWS
                              + (long long)ty * RPT;

    float r[4], pm[4], bc[4], jmp[4];
#pragma unroll
    for (int k = 0; k < 4; k++) {
        const int j = tx * 4 + k;
        const float a = A[j * N_COLS + j];            // diag (strictly negative)
        r[k]   = __expf(a);                           // per-row decay ratio
        jmp[k] = exp2f(hop_rows * a * LOG2E);         // chunk-hop factor
        pm[k]  = exp2f((float)first_row * a * LOG2E); // exact anchor
        bc[k]  = B[j] * C[j];
    }

    for (int c = blockIdx.x; c < nchunks; c += gridDim.x) {
        long long base = ((long long)c * CHUNK_ROWS + (long long)ty * RPT)
                       * CGROUPS + tx;
#pragma unroll
        for (int l = 0; l < RPT; l++) {
            float4 v;
            v.x = fmaf(pm[0], bc[0], d);
            v.y = fmaf(pm[1], bc[1], d);
            v.z = fmaf(pm[2], bc[2], d);
            v.w = fmaf(pm[3], bc[3], d);
            __stcs(&out[base], v);                    // streaming store
            base += CGROUPS;
            pm[0] *= r[0];
            pm[1] *= r[1];
            pm[2] *= r[2];
            pm[3] *= r[3];
        }
        // hop to this thread's rows in the next grid-stride chunk
        pm[0] *= jmp[0];
        pm[1] *= jmp[1];
        pm[2] *= jmp[2];
        pm[3] *= jmp[3];
    }
}

extern "C" void kernel_launch(void* const* d_in, const int* in_sizes, int n_in,
                              void* d_out, int out_size)
{
    // Inputs per reference order: (optional scalar L), A (n*n), B (n), C (n), D (1)
    int base = 0;
    if (n_in >= 5) base = n_in - 4;
    const float* A = (const float*)d_in[base + 0];
    const float* B = (const float*)d_in[base + 1];
    const float* C = (const float*)d_in[base + 2];
    const float* D = (const float*)d_in[base + 3];

    const long long L = (long long)out_size / N_COLS;   // 262144
    const int nchunks = (int)(L / CHUNK_ROWS);          // 4096

    ssm_kernel<<<GRID_BLOCKS, 256>>>(A, B, C, D, (float4*)d_out, nchunks);
}